// round 3
// baseline (speedup 1.0000x reference)
#include <cuda_runtime.h>

// SpecEMA single-pass decoupled-lookback scan, float4-vectorized, no smem staging.
// s_t = (1-a)*|x_t|^2 + a*s_{t-1},  y_t = x_t * rsqrt(s_t)
#define BB 64
#define CC 2
#define TT 4000
#define FF 96
#define NF4 24              // FF / 4
#define LCH 80              // timesteps per block-chunk
#define NCH 50              // TT / LCH
#define NSUB 4              // time sub-chunks per block
#define LS 20               // LCH / NSUB

#define ALPHA_F 0.99f
#define OMA_F ((float)(1.0 - 0.99))   // float32(1 - 0.99), matches jax

__host__ __device__ constexpr float fpow(float a, int n) {
    float r = 1.0f;
    for (int i = 0; i < n; i++) r *= a;
    return r;
}

// ---- scratch (__device__ globals; allocation-free rule) ----
__device__ float4 g_agg[BB * NCH * NF4];   // chunk aggregate (from s=0)
__device__ float4 g_inc[BB * NCH * NF4];   // inclusive state at chunk end
__device__ int    g_flag[BB * NCH];        // 0=empty 1=agg 2=inclusive
__device__ unsigned g_ctr;

__device__ __forceinline__ int ld_acquire(const int* p) {
    int v;
    asm volatile("ld.global.acquire.gpu.b32 %0, [%1];" : "=r"(v) : "l"(p));
    return v;
}
__device__ __forceinline__ void st_release(int* p, int v) {
    asm volatile("st.global.release.gpu.b32 [%0], %1;" :: "l"(p), "r"(v));
}

// one EMA step on 4 lanes
#define EMA4(s, a, c)                                                     \
    (s).x = fmaf(fmaf((a).x, (a).x, (c).x * (c).x), OMA_F, (s).x * ALPHA_F); \
    (s).y = fmaf(fmaf((a).y, (a).y, (c).y * (c).y), OMA_F, (s).y * ALPHA_F); \
    (s).z = fmaf(fmaf((a).z, (a).z, (c).z * (c).z), OMA_F, (s).z * ALPHA_F); \
    (s).w = fmaf(fmaf((a).w, (a).w, (c).w * (c).w), OMA_F, (s).w * ALPHA_F)

#define FMA4(acc, w, v)                      \
    (acc).x = fmaf((w), (v).x, (acc).x);     \
    (acc).y = fmaf((w), (v).y, (acc).y);     \
    (acc).z = fmaf((w), (v).z, (acc).z);     \
    (acc).w = fmaf((w), (v).w, (acc).w)

// ---------------- reset (graph replays reuse globals) ----------------
__global__ void k_reset() {
    int i = blockIdx.x * blockDim.x + threadIdx.x;
    if (i < BB * NCH) g_flag[i] = 0;
    if (i == 0) g_ctr = 0u;
}

// ---------------- single-pass scan ----------------
__global__ void __launch_bounds__(96) k_scan(const float* __restrict__ x,
                                             const float* __restrict__ state,
                                             float* __restrict__ out,
                                             float* __restrict__ fstate,
                                             int write_state) {
    __shared__ float4 sA[NSUB][NF4];
    __shared__ unsigned s_vbid;

    const int tid = threadIdx.x;
    if (tid == 0) s_vbid = atomicAdd(&g_ctr, 1u);
    __syncthreads();
    const int vbid = (int)s_vbid;
    const int b   = vbid % BB;     // b fastest -> preds scheduled first
    const int j   = vbid / BB;
    const int f4  = tid % NF4;
    const int sub = tid / NF4;

    const float aLS = fpow(ALPHA_F, LS);    // alpha^20
    const float aB  = fpow(ALPHA_F, LCH);   // alpha^80

    const size_t e0 = (((size_t)b * CC + 0) * TT + (size_t)j * LCH + sub * LS) * FF + f4 * 4;
    const size_t e1 = (((size_t)b * CC + 1) * TT + (size_t)j * LCH + sub * LS) * FF + f4 * 4;
    const float4* p0 = (const float4*)(x + e0);   // row stride NF4 float4s
    const float4* p1 = (const float4*)(x + e1);

    // ---- phase 1: sub-chunk aggregate from s=0 (x read #1) ----
    float4 part = make_float4(0.f, 0.f, 0.f, 0.f);
#pragma unroll 5
    for (int t = 0; t < LS; t++) {
        float4 a = p0[t * NF4];
        float4 c = p1[t * NF4];
        EMA4(part, a, c);
    }
    sA[sub][f4] = part;
    __syncthreads();

    // block aggregate (all threads; cheap smem reads)
    float4 A = sA[0][f4];
#pragma unroll
    for (int k = 1; k < NSUB; k++) {
        float4 t4 = sA[k][f4];
        A.x = fmaf(A.x, aLS, t4.x);
        A.y = fmaf(A.y, aLS, t4.y);
        A.z = fmaf(A.z, aLS, t4.z);
        A.w = fmaf(A.w, aLS, t4.w);
    }

    const int chain = b * NCH + j;
    if (sub == 0) {                       // tids 0..23, all in warp 0
        g_agg[chain * NF4 + f4] = A;
        __syncwarp(0x00FFFFFFu);
        if (tid == 0) { __threadfence(); st_release(&g_flag[chain], 1); }
    }

    // ---- phase 2: barrier-free lookback (every thread independently) ----
    float4 S;
    if (j == 0) {
        S = *(const float4*)(state + f4 * 4);
    } else {
        float4 acc = make_float4(0.f, 0.f, 0.f, 0.f);
        float w = 1.0f;
        int k = j - 1;
        for (;;) {
            const int* fl = &g_flag[b * NCH + k];
            int st = ld_acquire(fl);
            int spins = 0;
            while (st == 0) {
                if (++spins > 8) { __nanosleep(128); spins = 0; }
                st = ld_acquire(fl);
            }
            if (st == 2) {
                float4 v = g_inc[(b * NCH + k) * NF4 + f4];
                FMA4(acc, w, v);
                break;
            }
            float4 v = g_agg[(b * NCH + k) * NF4 + f4];
            FMA4(acc, w, v);
            w *= aB;
            if (k == 0) {
                float4 s0 = *(const float4*)(state + f4 * 4);
                FMA4(acc, w, s0);
                break;
            }
            k--;
        }
        S = acc;
    }

    // ---- publish inclusive ASAP (unblocks successors before our stores) ----
    if (sub == 0) {
        float4 inc;
        inc.x = fmaf(aB, S.x, A.x);
        inc.y = fmaf(aB, S.y, A.y);
        inc.z = fmaf(aB, S.z, A.z);
        inc.w = fmaf(aB, S.w, A.w);
        g_inc[chain * NF4 + f4] = inc;
        __syncwarp(0x00FFFFFFu);
        if (tid == 0) { __threadfence(); st_release(&g_flag[chain], 2); }
    }

    // ---- per-sub start: s = A_{k} + aLS * s, k = 0..sub-1 ----
    float4 s4 = S;
    for (int k = 0; k < sub; k++) {
        float4 Ak = sA[k][f4];
        s4.x = fmaf(aLS, s4.x, Ak.x);
        s4.y = fmaf(aLS, s4.y, Ak.y);
        s4.z = fmaf(aLS, s4.z, Ak.z);
        s4.w = fmaf(aLS, s4.w, Ak.w);
    }

    // ---- phase 3: replay (x read #2, L2-hot), write outputs ----
    float4* o0 = (float4*)(out + e0);
    float4* o1 = (float4*)(out + e1);
#pragma unroll 5
    for (int t = 0; t < LS; t++) {
        float4 a = p0[t * NF4];
        float4 c = p1[t * NF4];
        EMA4(s4, a, c);
        float4 r;
        r.x = rsqrtf(s4.x); r.y = rsqrtf(s4.y);
        r.z = rsqrtf(s4.z); r.w = rsqrtf(s4.w);
        float4 y0, y1;
        y0.x = a.x * r.x; y0.y = a.y * r.y; y0.z = a.z * r.z; y0.w = a.w * r.w;
        y1.x = c.x * r.x; y1.y = c.y * r.y; y1.z = c.z * r.z; y1.w = c.w * r.w;
        o0[t * NF4] = y0;
        o1[t * NF4] = y1;
    }

    if (write_state && j == NCH - 1 && sub == NSUB - 1) {
        *(float4*)(fstate + b * FF + f4 * 4) = s4;
    }
}

extern "C" void kernel_launch(void* const* d_in, const int* in_sizes, int n_in,
                              void* d_out, int out_size) {
    const float* feat  = (const float*)d_in[0];   // [B,C,T,F] f32
    const float* state = (const float*)d_in[1];   // [1,1,F]   f32
    float* out = (float*)d_out;

    const int n_out_main = BB * CC * TT * FF;     // 49,152,000
    int write_state = (out_size >= n_out_main + BB * FF) ? 1 : 0;
    float* fstate = out + n_out_main;

    k_reset<<<(BB * NCH + 255) / 256, 256>>>();
    k_scan<<<BB * NCH, 96>>>(feat, state, out, fstate, write_state);
}